// round 14
// baseline (speedup 1.0000x reference)
#include <cuda_runtime.h>
#include <math.h>
#include <limits.h>

#define H 128
#define W 128
#define B 8
#define G_EMPTY 40000      // > MAX_D2, fits u16: empty-row sentinel
#define MAX_D2 (127*127 + 127*127)

// Cross-kernel 1D row-distance table (u16).
__device__ unsigned short g_G[H * W];

// ---------- K1: 16 fat CTAs (8 rows each) -> union mask -> bit trick -> g_G ---
__global__ void __launch_bounds__(1024, 1)
edt_g(const float* __restrict__ in) {
    const int tid = threadIdx.x;
    const int j   = tid & 127;             // column
    const int q   = tid >> 7;              // row slot 0..7
    const int row = blockIdx.x * 8 + q;

#if __CUDA_ARCH__ >= 900
    // Let K2's grid begin launching immediately; K2 gates on full K1 completion
    // via cudaGridDependencySynchronize().
    cudaTriggerProgrammaticLaunchCompletion();
#endif

    __shared__ unsigned s_w[8][4];

    float m = __ldg(&in[row * W + j]);
#pragma unroll
    for (int b = 1; b < B; b++)
        m = fmaxf(m, __ldg(&in[b * (H * W) + row * W + j]));
    unsigned bal = __ballot_sync(0xFFFFFFFFu, m > 0.5f);
    if ((tid & 31) == 0)
        s_w[q][(tid >> 5) & 3] = bal;      // warp w -> row (w>>2), word (w&3)
    __syncthreads();

    unsigned long long lo = s_w[q][0] | ((unsigned long long)s_w[q][1] << 32);
    unsigned long long hi = s_w[q][2] | ((unsigned long long)s_w[q][3] << 32);
    int dr, dl;
    if (j < 64) {                          // warp-uniform branch
        unsigned long long t = lo >> j;
        dr = t ? (__ffsll((long long)t) - 1)
               : (hi ? (64 - j) + __ffsll((long long)hi) - 1 : 1024);
        unsigned long long u = lo << (63 - j);
        dl = u ? __clzll((long long)u) : 1024;
    } else {
        unsigned long long t = hi >> (j - 64);
        dr = t ? (__ffsll((long long)t) - 1) : 1024;
        unsigned long long u = hi << (127 - j);
        dl = u ? __clzll((long long)u)
               : (lo ? (j - 63) + __clzll((long long)lo) : 1024);
    }
    int d = min(dl, dr);
    g_G[row * W + j] = (d > 127) ? (unsigned short)G_EMPTY
                                 : (unsigned short)(d * d);
}

// ---------- K2 (PDL secondary): column pass + sqrt + broadcast (unchanged) ----
__global__ void __launch_bounds__(512, 1)
edt_d(float* __restrict__ out) {
    const int tid = threadIdx.x;
    const int j   = tid & 127;   // column
    const int p   = tid >> 7;    // quarter 0..3
    const int row = blockIdx.x;  // output row i

    __shared__ int s_part[4][W];
    __shared__ float s_res[W];

#if __CUDA_ARCH__ >= 900
    cudaGridDependencySynchronize();   // K1 done + g_G visible
#endif

    {
        const int hbase = p << 5;
        int best = INT_MAX;
#pragma unroll
        for (int k = 0; k < 32; k++) {
            int h  = hbase + k;
            int dh = row - h;
            int gv = (int)__ldcg(&g_G[h * W + j]);   // coalesced u16, MLP=32
            best = min(best, dh * dh + gv);
        }
        s_part[p][j] = best;
    }
    __syncthreads();

    if (tid < 128) {
        int b4 = min(min(s_part[0][j], s_part[1][j]),
                     min(s_part[2][j], s_part[3][j]));
        s_res[j] = (b4 > MAX_D2) ? INFINITY : sqrtf((float)b4);
    }
    __syncthreads();
    {
        float r = s_res[j];
        out[(2 * p)     * (H * W) + row * W + j] = r;
        out[(2 * p + 1) * (H * W) + row * W + j] = r;
    }
}

extern "C" void kernel_launch(void* const* d_in, const int* in_sizes, int n_in,
                              void* d_out, int out_size) {
    const float* in = (const float*)d_in[0];
    float* out = (float*)d_out;

    edt_g<<<16, 1024>>>(in);

    // Secondary with programmatic dependent launch: its ramp overlaps K1.
    cudaLaunchConfig_t cfg = {};
    cfg.gridDim  = dim3(H, 1, 1);
    cfg.blockDim = dim3(512, 1, 1);
    cfg.dynamicSmemBytes = 0;
    cfg.stream = 0;   // same (legacy default) stream as K1 for capture order
    cudaLaunchAttribute attr[1];
    attr[0].id = cudaLaunchAttributeProgrammaticStreamSerialization;
    attr[0].val.programmaticStreamSerializationAllowed = 1;
    cfg.attrs = attr;
    cfg.numAttrs = 1;
    cudaLaunchKernelEx(&cfg, edt_d, out);
}

// round 15
// speedup vs baseline: 1.0037x; 1.0037x over previous
#include <cuda_runtime.h>
#include <math.h>
#include <limits.h>

#define H 128
#define W 128
#define B 8
#define G_EMPTY 40000      // > MAX_D2, fits u16: empty-row sentinel
#define MAX_D2 (127*127 + 127*127)

// Cross-kernel 1D row-distance table (u16).
__device__ unsigned short g_G[H * W];

// ---------- K1: per-row union mask -> nearest-set-bit distance -> g_G --------
__global__ void __launch_bounds__(128, 1)
edt_g(const float* __restrict__ in) {
    const int j   = threadIdx.x;
    const int row = blockIdx.x;

#if __CUDA_ARCH__ >= 900
    // Let K2's grid begin its launch ramp immediately; K2 gates on full K1
    // completion via cudaGridDependencySynchronize().
    cudaTriggerProgrammaticLaunchCompletion();
#endif

    __shared__ unsigned s_w[4];

    float m = __ldg(&in[row * W + j]);
#pragma unroll
    for (int b = 1; b < B; b++)
        m = fmaxf(m, __ldg(&in[b * (H * W) + row * W + j]));
    unsigned bal = __ballot_sync(0xFFFFFFFFu, m > 0.5f);
    if ((j & 31) == 0) s_w[j >> 5] = bal;
    __syncthreads();

    unsigned long long lo = s_w[0] | ((unsigned long long)s_w[1] << 32);
    unsigned long long hi = s_w[2] | ((unsigned long long)s_w[3] << 32);
    int dr, dl;
    if (j < 64) {                            // warp-uniform branch
        unsigned long long t = lo >> j;
        dr = t ? (__ffsll((long long)t) - 1)
               : (hi ? (64 - j) + __ffsll((long long)hi) - 1 : 1024);
        unsigned long long u = lo << (63 - j);
        dl = u ? __clzll((long long)u) : 1024;
    } else {
        unsigned long long t = hi >> (j - 64);
        dr = t ? (__ffsll((long long)t) - 1) : 1024;
        unsigned long long u = hi << (127 - j);
        dl = u ? __clzll((long long)u)
               : (lo ? (j - 63) + __clzll((long long)lo) : 1024);
    }
    int d = min(dl, dr);
    g_G[row * W + j] = (d > 127) ? (unsigned short)G_EMPTY
                                 : (unsigned short)(d * d);
}

// ---------- K2 (PDL secondary): column pass + sqrt + broadcast ----------------
__global__ void __launch_bounds__(512, 1)
edt_d(float* __restrict__ out) {
    const int tid = threadIdx.x;
    const int j   = tid & 127;   // column
    const int p   = tid >> 7;    // quarter 0..3
    const int row = blockIdx.x;  // output row i

    __shared__ int s_part[4][W];

#if __CUDA_ARCH__ >= 900
    cudaGridDependencySynchronize();   // K1 done + g_G visible
#endif

    {
        const int hbase = p << 5;
        int best = INT_MAX;
#pragma unroll
        for (int k = 0; k < 32; k++) {
            int h  = hbase + k;
            int dh = row - h;
            int gv = (int)__ldcg(&g_G[h * W + j]);   // coalesced u16, MLP=32
            best = min(best, dh * dh + gv);
        }
        s_part[p][j] = best;
    }
    __syncthreads();

    // All 512 threads redundantly reduce (LDS broadcast) + sqrt: no second sync.
    {
        int b4 = min(min(s_part[0][j], s_part[1][j]),
                     min(s_part[2][j], s_part[3][j]));
        float r = (b4 > MAX_D2) ? INFINITY : sqrtf((float)b4);
        out[(2 * p)     * (H * W) + row * W + j] = r;
        out[(2 * p + 1) * (H * W) + row * W + j] = r;
    }
}

extern "C" void kernel_launch(void* const* d_in, const int* in_sizes, int n_in,
                              void* d_out, int out_size) {
    const float* in = (const float*)d_in[0];
    float* out = (float*)d_out;

    edt_g<<<H, 128>>>(in);

    // Secondary with programmatic dependent launch: its ramp overlaps K1.
    cudaLaunchConfig_t cfg = {};
    cfg.gridDim  = dim3(H, 1, 1);
    cfg.blockDim = dim3(512, 1, 1);
    cfg.dynamicSmemBytes = 0;
    cfg.stream = 0;   // same (legacy default) stream as K1 for capture order
    cudaLaunchAttribute attr[1];
    attr[0].id = cudaLaunchAttributeProgrammaticStreamSerialization;
    attr[0].val.programmaticStreamSerializationAllowed = 1;
    cfg.attrs = attr;
    cfg.numAttrs = 1;
    cudaLaunchKernelEx(&cfg, edt_d, out);
}